// round 1
// baseline (speedup 1.0000x reference)
#include <cuda_runtime.h>

// out[i, :] = weight[b[i], :]  for i in [0, N), Y_DIM = 32 floats = 8 float4
// out[0, :] = 0
//
// One thread per float4 (16B) of output: tid -> (cell = tid>>3, j = tid&7).
// Pure HBM-streaming kernel; weight (8 KB) is cache-resident.

__global__ __launch_bounds__(256, 8)
void batch_effect_kernel(const int* __restrict__ b,
                         const float4* __restrict__ w,
                         float4* __restrict__ out,
                         int n_cells)
{
    long long tid = (long long)blockIdx.x * blockDim.x + threadIdx.x;
    long long total = (long long)n_cells * 8;
    if (tid >= total) return;

    int cell = (int)(tid >> 3);
    int j = (int)(tid & 7);

    int bi = __ldg(&b[cell]);
    float4 v = __ldg(&w[bi * 8 + j]);

    if (cell == 0) {
        v.x = 0.0f; v.y = 0.0f; v.z = 0.0f; v.w = 0.0f;
    }

    out[tid] = v;
}

extern "C" void kernel_launch(void* const* d_in, const int* in_sizes, int n_in,
                              void* d_out, int out_size)
{
    const int* b = (const int*)d_in[0];          // [N, 1] int32
    const float4* w = (const float4*)d_in[1];    // [64, 32] float32 -> 64 rows of 8 float4
    float4* out = (float4*)d_out;                // [N, 32] float32

    int n_cells = in_sizes[0];                   // N (b has N elements)
    long long total_threads = (long long)n_cells * 8;
    int block = 256;
    int grid = (int)((total_threads + block - 1) / block);

    batch_effect_kernel<<<grid, block>>>(b, w, out, n_cells);
}

// round 2
// speedup vs baseline: 1.3367x; 1.3367x over previous
#include <cuda_runtime.h>

// out[i, :] = weight[b[i], :]  for i in [0, N), Y_DIM = 32 floats = 8 float4
// out[0, :] = 0
//
// Latency-bound fix vs R1:
//  - U=8 block-strided chunks per thread -> 8 independent index LDGs (MLP=8)
//  - weight (8KB) staged in shared memory -> dependent load is LDS (29cyc)
//    instead of LDG (234+cyc), collapsing the 2-deep long-scoreboard chain
//  - pure 32-bit indexing (8M chunks < 2^31)

constexpr int BLOCK = 256;
constexpr int U = 8;

__global__ __launch_bounds__(BLOCK)
void batch_effect_kernel(const int* __restrict__ b,
                         const float4* __restrict__ w,
                         float4* __restrict__ out,
                         unsigned int total_chunks)
{
    __shared__ float4 sw[512];            // 64 rows x 8 float4 = 8 KB
    #pragma unroll
    for (int i = threadIdx.x; i < 512; i += BLOCK)
        sw[i] = w[i];
    __syncthreads();

    unsigned int base = blockIdx.x * (BLOCK * U) + threadIdx.x;

    if (base + (U - 1) * BLOCK < total_chunks) {
        // Full tile: batch all 8 index loads first (8 outstanding LDGs),
        // then gather from smem and store.
        int bi[U];
        #pragma unroll
        for (int u = 0; u < U; u++) {
            unsigned int t = base + u * BLOCK;
            bi[u] = __ldg(&b[t >> 3]);
        }
        #pragma unroll
        for (int u = 0; u < U; u++) {
            unsigned int t = base + u * BLOCK;
            float4 v = sw[((unsigned)bi[u] << 3) | (t & 7u)];
            if (t < 8u) v = make_float4(0.f, 0.f, 0.f, 0.f);
            out[t] = v;
        }
    } else {
        // Tail tile
        #pragma unroll
        for (int u = 0; u < U; u++) {
            unsigned int t = base + u * BLOCK;
            if (t < total_chunks) {
                int bi = __ldg(&b[t >> 3]);
                float4 v = sw[((unsigned)bi << 3) | (t & 7u)];
                if (t < 8u) v = make_float4(0.f, 0.f, 0.f, 0.f);
                out[t] = v;
            }
        }
    }
}

extern "C" void kernel_launch(void* const* d_in, const int* in_sizes, int n_in,
                              void* d_out, int out_size)
{
    const int* b = (const int*)d_in[0];          // [N, 1] int32
    const float4* w = (const float4*)d_in[1];    // [64, 32] f32 = 512 float4
    float4* out = (float4*)d_out;                // [N, 32] f32 = N*8 float4

    unsigned int n_cells = (unsigned int)in_sizes[0];
    unsigned int total_chunks = n_cells * 8u;            // 8e6, fits in u32
    unsigned int per_block = BLOCK * U;                  // 2048 chunks per CTA
    unsigned int grid = (total_chunks + per_block - 1) / per_block;

    batch_effect_kernel<<<grid, BLOCK>>>(b, w, out, total_chunks);
}